// round 9
// baseline (speedup 1.0000x reference)
#include <cuda_runtime.h>
#include <cuda_fp16.h>
#include <cstdint>
#include <math.h>

#define B_ 8192
#define D_ 512
#define C_ 1000
#define CP_ 1024
#define CPS 1032     // padded smem stride (floats)
#define K_ 8
#define EPSV 1e-8f
#define TEMPV 0.2f
#define NEGV -10000.0f

// ---------------------------------------------------------------------------
// Scratch (__device__ globals)
// ---------------------------------------------------------------------------
__device__ __half g_z0[(size_t)B_ * D_];
__device__ __half g_z1[(size_t)B_ * D_];
__device__ __half g_w1t0[(size_t)K_ * D_ * D_];
__device__ __half g_w1t1[(size_t)K_ * D_ * D_];
__device__ __half g_w2t0[(size_t)K_ * CP_ * D_];
__device__ __half g_w2t1[(size_t)K_ * CP_ * D_];
__device__ __half g_h0[(size_t)K_ * B_ * D_];
__device__ __half g_h1[(size_t)K_ * B_ * D_];
__device__ float g_logits[(size_t)B_ * K_ * CP_];

// ---------------------------------------------------------------------------
// PTX helpers
// ---------------------------------------------------------------------------
__device__ __forceinline__ uint32_t smem_u32(const void* p) {
    uint32_t a;
    asm("{ .reg .u64 t; cvta.to.shared.u64 t, %1; cvt.u32.u64 %0, t; }" : "=r"(a) : "l"(p));
    return a;
}
__device__ __forceinline__ void cp_async16(uint32_t s, const void* g) {
    asm volatile("cp.async.cg.shared.global [%0], [%1], 16;" :: "r"(s), "l"(g));
}
__device__ __forceinline__ void cp_commit() { asm volatile("cp.async.commit_group;"); }
template <int N>
__device__ __forceinline__ void cp_wait() { asm volatile("cp.async.wait_group %0;" :: "n"(N)); }

__device__ __forceinline__ void ldsm4(uint32_t* r, uint32_t addr) {
    asm volatile("ldmatrix.sync.aligned.m8n8.x4.shared.b16 {%0,%1,%2,%3}, [%4];"
                 : "=r"(r[0]), "=r"(r[1]), "=r"(r[2]), "=r"(r[3]) : "r"(addr));
}
__device__ __forceinline__ void mma16816(float* c, const uint32_t* a, uint32_t b0, uint32_t b1) {
    asm volatile(
        "mma.sync.aligned.m16n8k16.row.col.f32.f16.f16.f32 "
        "{%0,%1,%2,%3}, {%4,%5,%6,%7}, {%8,%9}, {%0,%1,%2,%3};"
        : "+f"(c[0]), "+f"(c[1]), "+f"(c[2]), "+f"(c[3])
        : "r"(a[0]), "r"(a[1]), "r"(a[2]), "r"(a[3]), "r"(b0), "r"(b1));
}

// 2-limb fp16 split: x = a + b + O(2^-22 |x|)
__device__ __forceinline__ void split2(float x, __half& a, __half& b) {
    a = __float2half_rn(x);
    b = __float2half_rn(x - __half2float(a));
}

// ---------------------------------------------------------------------------
// Conversion kernels
// ---------------------------------------------------------------------------
__global__ void split2_kernel(const float* __restrict__ x, __half* __restrict__ o0,
                              __half* __restrict__ o1, int n4) {
    int i = blockIdx.x * blockDim.x + threadIdx.x;
    if (i < n4) {
        float4 v = ((const float4*)x)[i];
        __half a0, b0, a1, b1, a2, b2, a3, b3;
        split2(v.x, a0, b0); split2(v.y, a1, b1);
        split2(v.z, a2, b2); split2(v.w, a3, b3);
        ((__half2*)o0)[i * 2]     = __half2(a0, a1);
        ((__half2*)o0)[i * 2 + 1] = __half2(a2, a3);
        ((__half2*)o1)[i * 2]     = __half2(b0, b1);
        ((__half2*)o1)[i * 2 + 1] = __half2(b2, b3);
    }
}

// in: [K][D_][Nin] fp32 -> out: [K][Npad][D_] fp16 x2 (transposed, rows >= Nin zeroed)
__global__ void trsplit_kernel(const float* __restrict__ in, __half* __restrict__ o0,
                               __half* __restrict__ o1, int Nin, int Npad) {
    __shared__ float t[32][33];
    const int k = blockIdx.z;
    const int n0 = blockIdx.x * 32, d0 = blockIdx.y * 32;
    const int tx = threadIdx.x, ty = threadIdx.y;
    const float* src = in + (size_t)k * D_ * Nin;
#pragma unroll
    for (int r = 0; r < 4; r++) {
        int d = d0 + ty + r * 8, n = n0 + tx;
        t[ty + r * 8][tx] = (n < Nin) ? src[(size_t)d * Nin + n] : 0.0f;
    }
    __syncthreads();
    size_t obase = (size_t)k * Npad * D_;
#pragma unroll
    for (int r = 0; r < 4; r++) {
        int nl = ty + r * 8;
        float v = t[tx][nl];
        __half a, b;
        split2(v, a, b);
        size_t oi = obase + (size_t)(n0 + nl) * D_ + d0 + tx;
        o0[oi] = a; o1[oi] = b;
    }
}

// ---------------------------------------------------------------------------
// HMMA fp16 GEMM with 3-product 2-limb split.
// Block 128x128, BK=32, 256 threads (8 warps: 2x4), warp tile 64x32.
// 3-stage cp.async pipeline, XOR-swizzled packed smem, 2 CTAs/SM.
// Smem-staged coalesced epilogue.
// ---------------------------------------------------------------------------
#define TILE_B 8192                  // 128 rows x 64 B
#define STAGE_B (4 * TILE_B)         // 32768 B (A0,A1,B0,B1)
#define NSTAGE 3
#define NCHUNK 16                    // 512 / 32
#define EPI_PITCH_H 272              // bytes/row per half-limb tile (conflict-free)
#define EPI_PITCH_F 528              // bytes/row for fp32 tile (132 floats)

template <bool SPLIT>
__global__ void __launch_bounds__(256, 2) tc_gemm(
    const __half* __restrict__ A0, const __half* __restrict__ A1, long long aStr,
    const __half* __restrict__ B0, const __half* __restrict__ B1, long long bStr,
    const float* __restrict__ bias, int biasStr, int Nreal,
    float* __restrict__ outF, int outLd,
    __half* __restrict__ O0, __half* __restrict__ O1)
{
    extern __shared__ __align__(16) char dsm[];
    const uint32_t sbase = smem_u32(dsm);

    const int tid = threadIdx.x;
    const int warp = tid >> 5, lane = tid & 31;
    const int bz = blockIdx.z;
    const int m0 = blockIdx.y * 128, n0 = blockIdx.x * 128;
    const int warpM = (warp >> 2) * 64;   // 0 or 64
    const int warpN = (warp & 3) * 32;    // 0,32,64,96

    const char* gp[4];
    gp[0] = (const char*)A0 + ((size_t)bz * aStr + (size_t)m0 * D_) * 2;
    gp[1] = (const char*)A1 + ((size_t)bz * aStr + (size_t)m0 * D_) * 2;
    gp[2] = (const char*)B0 + ((size_t)bz * bStr + (size_t)n0 * D_) * 2;
    gp[3] = (const char*)B1 + ((size_t)bz * bStr + (size_t)n0 * D_) * 2;

    // cp.async write mapping: 2 chunks of 16B per thread per tile
    const int ldRow0 = tid >> 2, ldC0 = tid & 3;
    const int ldRow1 = (tid + 256) >> 2, ldC1 = (tid + 256) & 3;
    const uint32_t ldDst0 = (uint32_t)ldRow0 * 64 + (uint32_t)((ldC0 ^ ((ldRow0 >> 1) & 3)) << 4);
    const uint32_t ldDst1 = (uint32_t)ldRow1 * 64 + (uint32_t)((ldC1 ^ ((ldRow1 >> 1) & 3)) << 4);
    const size_t ldSrc0 = (size_t)ldRow0 * 1024 + ldC0 * 16;
    const size_t ldSrc1 = (size_t)ldRow1 * 1024 + ldC1 * 16;

    auto load_stage = [&](int kk, int buf) {
        const size_t koff = (size_t)kk * 64;
#pragma unroll
        for (int t = 0; t < 4; t++) {
            uint32_t sb = sbase + buf * STAGE_B + t * TILE_B;
            const char* g = gp[t] + koff;
            cp_async16(sb + ldDst0, g + ldSrc0);
            cp_async16(sb + ldDst1, g + ldSrc1);
        }
        cp_commit();
    };

    float acc[4][4][4];
#pragma unroll
    for (int i = 0; i < 4; i++)
#pragma unroll
        for (int j = 0; j < 4; j++)
#pragma unroll
            for (int r = 0; r < 4; r++) acc[i][j][r] = 0.0f;

    load_stage(0, 0);
    load_stage(1, 1);

    const int rowA = warpM + (lane & 15);
    const uint32_t swA = (uint32_t)((rowA >> 1) & 3);
    const uint32_t cA = (uint32_t)(lane >> 4);
    const uint32_t aBase = (uint32_t)rowA * 64;

    const int rowB = warpN + (lane & 7) + ((lane >> 4) & 1) * 8;
    const uint32_t swB = (uint32_t)((rowB >> 1) & 3);
    const uint32_t cB = (uint32_t)((lane >> 3) & 1);
    const uint32_t bBase = (uint32_t)rowB * 64;

    for (int kk = 0; kk < NCHUNK; kk++) {
        if (kk == NCHUNK - 1) cp_wait<0>(); else cp_wait<1>();
        __syncthreads();
        if (kk + 2 < NCHUNK) load_stage(kk + 2, (kk + 2) % NSTAGE);

        const uint32_t sb = sbase + (kk % NSTAGE) * STAGE_B;

#pragma unroll
        for (int ks = 0; ks < 2; ks++) {
            const uint32_t aOff = aBase + (((ks * 2 + cA) ^ swA) << 4);
            const uint32_t bOff = bBase + (((ks * 2 + cB) ^ swB) << 4);
            uint32_t a0f[4][4], b0f[2][4];
#pragma unroll
            for (int i = 0; i < 4; i++)
                ldsm4(a0f[i], sb + 0 * TILE_B + aOff + i * 1024);
#pragma unroll
            for (int jp = 0; jp < 2; jp++)
                ldsm4(b0f[jp], sb + 2 * TILE_B + bOff + jp * 1024);
#pragma unroll
            for (int i = 0; i < 4; i++)
#pragma unroll
                for (int j = 0; j < 4; j++)
                    mma16816(acc[i][j], a0f[i], b0f[j >> 1][(j & 1) * 2],
                             b0f[j >> 1][(j & 1) * 2 + 1]);
            {
                uint32_t b1f[2][4];
#pragma unroll
                for (int jp = 0; jp < 2; jp++)
                    ldsm4(b1f[jp], sb + 3 * TILE_B + bOff + jp * 1024);
#pragma unroll
                for (int i = 0; i < 4; i++)
#pragma unroll
                    for (int j = 0; j < 4; j++)
                        mma16816(acc[i][j], a0f[i], b1f[j >> 1][(j & 1) * 2],
                                 b1f[j >> 1][(j & 1) * 2 + 1]);
            }
            {
                uint32_t a1f[4][4];
#pragma unroll
                for (int i = 0; i < 4; i++)
                    ldsm4(a1f[i], sb + 1 * TILE_B + aOff + i * 1024);
#pragma unroll
                for (int i = 0; i < 4; i++)
#pragma unroll
                    for (int j = 0; j < 4; j++)
                        mma16816(acc[i][j], a1f[i], b0f[j >> 1][(j & 1) * 2],
                                 b0f[j >> 1][(j & 1) * 2 + 1]);
            }
        }
    }

    // ---------------- epilogue: smem-staged, coalesced global writes --------
    __syncthreads();   // all mainloop smem reads complete; reuse dsm

    const int rBase = warpM + (lane >> 2);          // local row
    const int cBaseH = warpN + (lane & 3) * 2;      // local col

    // preload 8 bias values (n depends only on j/t)
    float bj[4][2];
#pragma unroll
    for (int j = 0; j < 4; j++)
#pragma unroll
        for (int t = 0; t < 2; t++) {
            int n = n0 + cBaseH + j * 8 + t;
            bj[j][t] = (SPLIT || n < Nreal) ? bias[bz * biasStr + n] : 0.0f;
        }

    if (SPLIT) {
        // two half-limb tiles, pitch 272B each
#pragma unroll
        for (int i = 0; i < 4; i++)
#pragma unroll
            for (int j = 0; j < 4; j++)
#pragma unroll
                for (int half = 0; half < 2; half++) {
                    const int r = rBase + i * 16 + half * 8;
                    const int c = cBaseH + j * 8;   // even
                    float v0 = fmaxf(acc[i][j][half * 2]     + bj[j][0], 0.0f);
                    float v1 = fmaxf(acc[i][j][half * 2 + 1] + bj[j][1], 0.0f);
                    __half a0, b0, a1, b1;
                    split2(v0, a0, b0);
                    split2(v1, a1, b1);
                    *(__half2*)(dsm + r * EPI_PITCH_H + c * 2) = __half2(a0, a1);
                    *(__half2*)(dsm + 128 * EPI_PITCH_H + r * EPI_PITCH_H + c * 2) = __half2(b0, b1);
                }
        __syncthreads();
        // coalesced write-out: 16B/thread, 256B/row segments
#pragma unroll
        for (int it = 0; it < 8; it++) {
            int idx = tid + it * 256;               // 0..2047
            int r = idx >> 4, c16 = idx & 15;
            float4 w0 = *(const float4*)(dsm + r * EPI_PITCH_H + c16 * 16);
            float4 w1 = *(const float4*)(dsm + 128 * EPI_PITCH_H + r * EPI_PITCH_H + c16 * 16);
            size_t gb = ((size_t)bz * B_ + m0 + r) * D_ + n0 + c16 * 8;
            *(float4*)&O0[gb] = w0;
            *(float4*)&O1[gb] = w1;
        }
    } else {
        // fp32 tile, pitch 528B
#pragma unroll
        for (int i = 0; i < 4; i++)
#pragma unroll
            for (int j = 0; j < 4; j++)
#pragma unroll
                for (int half = 0; half < 2; half++) {
                    const int r = rBase + i * 16 + half * 8;
                    const int c = cBaseH + j * 8;
                    float2 vv = make_float2(acc[i][j][half * 2]     + bj[j][0],
                                            acc[i][j][half * 2 + 1] + bj[j][1]);
                    *(float2*)(dsm + r * EPI_PITCH_F + c * 4) = vv;
                }
        __syncthreads();
#pragma unroll
        for (int it = 0; it < 16; it++) {
            int idx = tid + it * 256;               // 0..4095
            int r = idx >> 5, c4 = idx & 31;
            float4 w = *(const float4*)(dsm + r * EPI_PITCH_F + c4 * 16);
            *(float4*)&outF[((size_t)(m0 + r) * K_ + bz) * outLd + n0 + c4 * 4] = w;
        }
    }
}

// ---------------------------------------------------------------------------
// Gating kernel — vectorized float4; logits strided [b][k][CP_]
// ---------------------------------------------------------------------------
__global__ void __launch_bounds__(256) gating_kernel(
    const int* __restrict__ n_exp,
    float* __restrict__ out_logits,
    float* __restrict__ out_gates)
{
    extern __shared__ float sm[];
    float* sl = sm;               // [K_][CPS]
    float* se = sm + K_ * CPS;    // [K_][CPS]
    __shared__ float sZ[K_], sG[K_ * K_], sgate[K_];

    const int b = blockIdx.x, tid = threadIdx.x;
    const int w = tid >> 5, lane = tid & 31;

    const float* lrow = g_logits + (size_t)b * K_ * CP_;
#pragma unroll
    for (int it = 0; it < 8; it++) {
        int idx = tid + it * 256;
        int k = idx >> 8;
        int c4 = (idx & 255) * 4;
        float4 v = *(const float4*)(lrow + (size_t)k * CP_ + c4);
        *(float4*)(sl + k * CPS + c4) = v;
    }
    __syncthreads();

    {
        float m = -INFINITY;
#pragma unroll
        for (int it = 0; it < 8; it++) {
            int c = it * 128 + lane * 4;
            float4 v = *(const float4*)(sl + w * CPS + c);
            if (c + 0 < C_) m = fmaxf(m, v.x);
            if (c + 1 < C_) m = fmaxf(m, v.y);
            if (c + 2 < C_) m = fmaxf(m, v.z);
            if (c + 3 < C_) m = fmaxf(m, v.w);
        }
#pragma unroll
        for (int o = 16; o > 0; o >>= 1) m = fmaxf(m, __shfl_xor_sync(0xffffffffu, m, o));
        float z = 0.0f;
#pragma unroll
        for (int it = 0; it < 8; it++) {
            int c = it * 128 + lane * 4;
            float4 v = *(const float4*)(sl + w * CPS + c);
            float4 e;
            e.x = (c + 0 < C_) ? __expf(v.x - m) : 0.0f;
            e.y = (c + 1 < C_) ? __expf(v.y - m) : 0.0f;
            e.z = (c + 2 < C_) ? __expf(v.z - m) : 0.0f;
            e.w = (c + 3 < C_) ? __expf(v.w - m) : 0.0f;
            *(float4*)(se + w * CPS + c) = e;
            z += e.x + e.y + e.z + e.w;
        }
#pragma unroll
        for (int o = 16; o > 0; o >>= 1) z += __shfl_xor_sync(0xffffffffu, z, o);
        if (lane == 0) sZ[w] = z;
    }
    __syncthreads();

    for (int p = w; p < 36; p += 8) {
        int i = 0, q = p;
        while (q >= K_ - i) { q -= (K_ - i); i++; }
        int j = i + q;
        float s = 0.0f;
#pragma unroll
        for (int it = 0; it < 8; it++) {
            int c = it * 128 + lane * 4;
            float4 a = *(const float4*)(se + i * CPS + c);
            float4 bb = *(const float4*)(se + j * CPS + c);
            s += a.x * bb.x + a.y * bb.y + a.z * bb.z + a.w * bb.w;
        }
#pragma unroll
        for (int o = 16; o > 0; o >>= 1) s += __shfl_xor_sync(0xffffffffu, s, o);
        if (lane == 0) {
            float g = s / (sZ[i] * sZ[j]);
            sG[i * K_ + j] = g;
            sG[j * K_ + i] = g;
        }
    }
    __syncthreads();

    if (tid == 0) {
        float Smat[K_][K_], conf[K_], nrm[K_];
#pragma unroll
        for (int i = 0; i < K_; i++) {
            nrm[i] = sqrtf(sG[i * K_ + i]) + EPSV;
            conf[i] = 1.0f / sZ[i];
        }
#pragma unroll
        for (int i = 0; i < K_; i++)
#pragma unroll
            for (int j = 0; j < K_; j++)
                Smat[i][j] = sG[i * K_ + j] / (nrm[i] * nrm[j]);

        int bi = 0; float bv = conf[0];
#pragma unroll
        for (int i = 1; i < K_; i++) if (conf[i] > bv) { bv = conf[i]; bi = i; }
        bool sel[K_];
#pragma unroll
        for (int i = 0; i < K_; i++) sel[i] = false;
        sel[bi] = true;

        int n = n_exp[b];
        for (int t = 1; t < K_; t++) {
            float dist[K_];
#pragma unroll
            for (int i = 0; i < K_; i++) {
                if (sel[i]) dist[i] = -INFINITY;
                else {
                    float ms = -INFINITY;
#pragma unroll
                    for (int j = 0; j < K_; j++)
                        if (sel[j]) ms = fmaxf(ms, Smat[i][j]);
                    dist[i] = 1.0f - ms;
                }
            }
            int ai = 0; float av = dist[0];
#pragma unroll
            for (int i = 1; i < K_; i++) if (dist[i] > av) { av = dist[i]; ai = i; }
            if (t < n) sel[ai] = true;
        }

        float gl[K_], gm = -INFINITY;
#pragma unroll
        for (int i = 0; i < K_; i++) {
            gl[i] = (sel[i] ? conf[i] : NEGV) / TEMPV;
            gm = fmaxf(gm, gl[i]);
        }
        float gs = 0.0f;
#pragma unroll
        for (int i = 0; i < K_; i++) { gl[i] = __expf(gl[i] - gm); gs += gl[i]; }
#pragma unroll
        for (int i = 0; i < K_; i++) sgate[i] = gl[i] / gs;
    }
    __syncthreads();

    if (tid < 250) {
        int c = tid * 4;
        float4 acc4 = make_float4(0.f, 0.f, 0.f, 0.f);
#pragma unroll
        for (int k = 0; k < K_; k++) {
            float g = sgate[k];
            float4 v = *(const float4*)(sl + k * CPS + c);
            acc4.x += g * v.x; acc4.y += g * v.y;
            acc4.z += g * v.z; acc4.w += g * v.w;
        }
        *(float4*)(out_logits + (size_t)b * C_ + c) = acc4;
    }
    if (tid < K_) out_gates[(size_t)b * K_ + tid] = sgate[tid];
}

// ---------------------------------------------------------------------------
extern "C" void kernel_launch(void* const* d_in, const int* in_sizes, int n_in,
                              void* d_out, int out_size)
{
    const float* z    = (const float*)d_in[0];
    const int*   nexp = (const int*)d_in[1];
    const float* W1   = (const float*)d_in[2];
    const float* b1   = (const float*)d_in[3];
    const float* W2   = (const float*)d_in[4];
    const float* b2   = (const float*)d_in[5];
    float* out = (float*)d_out;

    __half *z0, *z1, *w10, *w11, *w20, *w21, *h0, *h1;
    float* lg;
    cudaGetSymbolAddress((void**)&z0, g_z0);   cudaGetSymbolAddress((void**)&z1, g_z1);
    cudaGetSymbolAddress((void**)&w10, g_w1t0); cudaGetSymbolAddress((void**)&w11, g_w1t1);
    cudaGetSymbolAddress((void**)&w20, g_w2t0); cudaGetSymbolAddress((void**)&w21, g_w2t1);
    cudaGetSymbolAddress((void**)&h0, g_h0);   cudaGetSymbolAddress((void**)&h1, g_h1);
    cudaGetSymbolAddress((void**)&lg, g_logits);

    const int gate_smem = 2 * K_ * CPS * sizeof(float);
    cudaFuncSetAttribute(tc_gemm<true>,  cudaFuncAttributeMaxDynamicSharedMemorySize, NSTAGE * STAGE_B);
    cudaFuncSetAttribute(tc_gemm<false>, cudaFuncAttributeMaxDynamicSharedMemorySize, NSTAGE * STAGE_B);
    cudaFuncSetAttribute(gating_kernel,  cudaFuncAttributeMaxDynamicSharedMemorySize, gate_smem);

    // input conversions
    split2_kernel<<<(B_ * D_ / 4 + 255) / 256, 256>>>(z, z0, z1, B_ * D_ / 4);
    trsplit_kernel<<<dim3(D_ / 32, D_ / 32, K_), dim3(32, 8)>>>(W1, w10, w11, D_, D_);
    trsplit_kernel<<<dim3(CP_ / 32, D_ / 32, K_), dim3(32, 8)>>>(W2, w20, w21, C_, CP_);

    // GEMM1: h = relu(z @ W1 + b1), re-split into 2 fp16 limbs
    tc_gemm<true><<<dim3(D_ / 128, B_ / 128, K_), 256, NSTAGE * STAGE_B>>>(
        z0, z1, 0LL,
        w10, w11, (long long)D_ * D_,
        b1, D_, D_, nullptr, 0, h0, h1);

    // GEMM2: logits = h @ W2 + b2 (fp32, padded to CP_)
    tc_gemm<false><<<dim3(CP_ / 128, B_ / 128, K_), 256, NSTAGE * STAGE_B>>>(
        h0, h1, (long long)B_ * D_,
        w20, w21, (long long)CP_ * D_,
        b2, C_, C_, lg, CP_, nullptr, nullptr);

    // gating + combine
    gating_kernel<<<B_, 256, gate_smem>>>(nexp, out, out + (size_t)B_ * C_);
}

// round 11
// speedup vs baseline: 1.1033x; 1.1033x over previous
#include <cuda_runtime.h>
#include <cuda_fp16.h>
#include <cstdint>
#include <math.h>

#define B_ 8192
#define D_ 512
#define C_ 1000
#define CP_ 1024
#define K_ 8
#define EPSV 1e-8f
#define TEMPV 0.2f
#define NEGV -10000.0f

// ---------------------------------------------------------------------------
// Scratch (__device__ globals)
// ---------------------------------------------------------------------------
__device__ __half g_z0[(size_t)B_ * D_];
__device__ __half g_z1[(size_t)B_ * D_];
__device__ __half g_w1t0[(size_t)K_ * D_ * D_];
__device__ __half g_w1t1[(size_t)K_ * D_ * D_];
__device__ __half g_w2t0[(size_t)K_ * CP_ * D_];
__device__ __half g_w2t1[(size_t)K_ * CP_ * D_];
__device__ __half g_h0[(size_t)K_ * B_ * D_];
__device__ __half g_h1[(size_t)K_ * B_ * D_];
__device__ float g_logits[(size_t)B_ * K_ * CP_];

// ---------------------------------------------------------------------------
// PTX helpers
// ---------------------------------------------------------------------------
__device__ __forceinline__ uint32_t smem_u32(const void* p) {
    uint32_t a;
    asm("{ .reg .u64 t; cvta.to.shared.u64 t, %1; cvt.u32.u64 %0, t; }" : "=r"(a) : "l"(p));
    return a;
}
__device__ __forceinline__ void cp_async16(uint32_t s, const void* g) {
    asm volatile("cp.async.cg.shared.global [%0], [%1], 16;" :: "r"(s), "l"(g));
}
__device__ __forceinline__ void cp_commit() { asm volatile("cp.async.commit_group;"); }
template <int N>
__device__ __forceinline__ void cp_wait() { asm volatile("cp.async.wait_group %0;" :: "n"(N)); }

__device__ __forceinline__ void ldsm4(uint32_t* r, uint32_t addr) {
    asm volatile("ldmatrix.sync.aligned.m8n8.x4.shared.b16 {%0,%1,%2,%3}, [%4];"
                 : "=r"(r[0]), "=r"(r[1]), "=r"(r[2]), "=r"(r[3]) : "r"(addr));
}
__device__ __forceinline__ void mma16816(float* c, const uint32_t* a, uint32_t b0, uint32_t b1) {
    asm volatile(
        "mma.sync.aligned.m16n8k16.row.col.f32.f16.f16.f32 "
        "{%0,%1,%2,%3}, {%4,%5,%6,%7}, {%8,%9}, {%0,%1,%2,%3};"
        : "+f"(c[0]), "+f"(c[1]), "+f"(c[2]), "+f"(c[3])
        : "r"(a[0]), "r"(a[1]), "r"(a[2]), "r"(a[3]), "r"(b0), "r"(b1));
}

// 2-limb fp16 split: x = a + b + O(2^-22 |x|)
__device__ __forceinline__ void split2(float x, __half& a, __half& b) {
    a = __float2half_rn(x);
    b = __float2half_rn(x - __half2float(a));
}

// ---------------------------------------------------------------------------
// Conversion kernels
// ---------------------------------------------------------------------------
__global__ void split2_kernel(const float* __restrict__ x, __half* __restrict__ o0,
                              __half* __restrict__ o1, int n4) {
    int i = blockIdx.x * blockDim.x + threadIdx.x;
    if (i < n4) {
        float4 v = ((const float4*)x)[i];
        __half a0, b0, a1, b1, a2, b2, a3, b3;
        split2(v.x, a0, b0); split2(v.y, a1, b1);
        split2(v.z, a2, b2); split2(v.w, a3, b3);
        ((__half2*)o0)[i * 2]     = __half2(a0, a1);
        ((__half2*)o0)[i * 2 + 1] = __half2(a2, a3);
        ((__half2*)o1)[i * 2]     = __half2(b0, b1);
        ((__half2*)o1)[i * 2 + 1] = __half2(b2, b3);
    }
}

// in: [K][D_][Nin] fp32 -> out: [K][Npad][D_] fp16 x2 (transposed, rows >= Nin zeroed)
__global__ void trsplit_kernel(const float* __restrict__ in, __half* __restrict__ o0,
                               __half* __restrict__ o1, int Nin, int Npad) {
    __shared__ float t[32][33];
    const int k = blockIdx.z;
    const int n0 = blockIdx.x * 32, d0 = blockIdx.y * 32;
    const int tx = threadIdx.x, ty = threadIdx.y;
    const float* src = in + (size_t)k * D_ * Nin;
#pragma unroll
    for (int r = 0; r < 4; r++) {
        int d = d0 + ty + r * 8, n = n0 + tx;
        t[ty + r * 8][tx] = (n < Nin) ? src[(size_t)d * Nin + n] : 0.0f;
    }
    __syncthreads();
    size_t obase = (size_t)k * Npad * D_;
#pragma unroll
    for (int r = 0; r < 4; r++) {
        int nl = ty + r * 8;
        float v = t[tx][nl];
        __half a, b;
        split2(v, a, b);
        size_t oi = obase + (size_t)(n0 + nl) * D_ + d0 + tx;
        o0[oi] = a; o1[oi] = b;
    }
}

// ---------------------------------------------------------------------------
// HMMA fp16 GEMM with 3-product 2-limb split.
// Block 128x128, BK=32, 256 threads (8 warps: 2x4), warp tile 64x32.
// 3-stage cp.async pipeline, XOR-swizzled packed smem, 2 CTAs/SM.
// Proven ordering: wait -> syncthreads -> issue next loads -> compute.
// ---------------------------------------------------------------------------
#define TILE_B 8192                  // 128 rows x 64 B
#define STAGE_B (4 * TILE_B)         // 32768 B (A0,A1,B0,B1)
#define NSTAGE 3
#define NCHUNK 16                    // 512 / 32
#define EPI_PITCH_H 272              // bytes/row per half-limb tile
#define EPI_PITCH_F 528              // bytes/row for fp32 tile

template <bool SPLIT>
__global__ void __launch_bounds__(256, 2) tc_gemm(
    const __half* __restrict__ A0, const __half* __restrict__ A1, long long aStr,
    const __half* __restrict__ B0, const __half* __restrict__ B1, long long bStr,
    const float* __restrict__ bias, int biasStr, int Nreal,
    float* __restrict__ outF, int outLd,
    __half* __restrict__ O0, __half* __restrict__ O1)
{
    extern __shared__ __align__(16) char dsm[];
    const uint32_t sbase = smem_u32(dsm);

    const int tid = threadIdx.x;
    const int warp = tid >> 5, lane = tid & 31;
    const int bz = blockIdx.z;
    const int m0 = blockIdx.y * 128, n0 = blockIdx.x * 128;
    const int warpM = (warp >> 2) * 64;
    const int warpN = (warp & 3) * 32;

    const char* gp[4];
    gp[0] = (const char*)A0 + ((size_t)bz * aStr + (size_t)m0 * D_) * 2;
    gp[1] = (const char*)A1 + ((size_t)bz * aStr + (size_t)m0 * D_) * 2;
    gp[2] = (const char*)B0 + ((size_t)bz * bStr + (size_t)n0 * D_) * 2;
    gp[3] = (const char*)B1 + ((size_t)bz * bStr + (size_t)n0 * D_) * 2;

    const int ldRow0 = tid >> 2, ldC0 = tid & 3;
    const int ldRow1 = (tid + 256) >> 2, ldC1 = (tid + 256) & 3;
    const uint32_t ldDst0 = (uint32_t)ldRow0 * 64 + (uint32_t)((ldC0 ^ ((ldRow0 >> 1) & 3)) << 4);
    const uint32_t ldDst1 = (uint32_t)ldRow1 * 64 + (uint32_t)((ldC1 ^ ((ldRow1 >> 1) & 3)) << 4);
    const size_t ldSrc0 = (size_t)ldRow0 * 1024 + ldC0 * 16;
    const size_t ldSrc1 = (size_t)ldRow1 * 1024 + ldC1 * 16;

    auto load_stage = [&](int kk, int buf) {
        const size_t koff = (size_t)kk * 64;
#pragma unroll
        for (int t = 0; t < 4; t++) {
            uint32_t sb = sbase + buf * STAGE_B + t * TILE_B;
            const char* g = gp[t] + koff;
            cp_async16(sb + ldDst0, g + ldSrc0);
            cp_async16(sb + ldDst1, g + ldSrc1);
        }
        cp_commit();
    };

    float acc[4][4][4];
#pragma unroll
    for (int i = 0; i < 4; i++)
#pragma unroll
        for (int j = 0; j < 4; j++)
#pragma unroll
            for (int r = 0; r < 4; r++) acc[i][j][r] = 0.0f;

    load_stage(0, 0);
    load_stage(1, 1);

    const int rowA = warpM + (lane & 15);
    const uint32_t swA = (uint32_t)((rowA >> 1) & 3);
    const uint32_t cA = (uint32_t)(lane >> 4);
    const uint32_t aBase = (uint32_t)rowA * 64;

    const int rowB = warpN + (lane & 7) + ((lane >> 4) & 1) * 8;
    const uint32_t swB = (uint32_t)((rowB >> 1) & 3);
    const uint32_t cB = (uint32_t)((lane >> 3) & 1);
    const uint32_t bBase = (uint32_t)rowB * 64;

    for (int kk = 0; kk < NCHUNK; kk++) {
        if (kk == NCHUNK - 1) cp_wait<0>(); else cp_wait<1>();
        __syncthreads();
        if (kk + 2 < NCHUNK) load_stage(kk + 2, (kk + 2) % NSTAGE);

        const uint32_t sb = sbase + (kk % NSTAGE) * STAGE_B;

#pragma unroll
        for (int ks = 0; ks < 2; ks++) {
            const uint32_t aOff = aBase + (((ks * 2 + cA) ^ swA) << 4);
            const uint32_t bOff = bBase + (((ks * 2 + cB) ^ swB) << 4);
            uint32_t a0f[4][4], b0f[2][4];
#pragma unroll
            for (int i = 0; i < 4; i++)
                ldsm4(a0f[i], sb + 0 * TILE_B + aOff + i * 1024);
#pragma unroll
            for (int jp = 0; jp < 2; jp++)
                ldsm4(b0f[jp], sb + 2 * TILE_B + bOff + jp * 1024);
#pragma unroll
            for (int i = 0; i < 4; i++)
#pragma unroll
                for (int j = 0; j < 4; j++)
                    mma16816(acc[i][j], a0f[i], b0f[j >> 1][(j & 1) * 2],
                             b0f[j >> 1][(j & 1) * 2 + 1]);
            {
                uint32_t b1f[2][4];
#pragma unroll
                for (int jp = 0; jp < 2; jp++)
                    ldsm4(b1f[jp], sb + 3 * TILE_B + bOff + jp * 1024);
#pragma unroll
                for (int i = 0; i < 4; i++)
#pragma unroll
                    for (int j = 0; j < 4; j++)
                        mma16816(acc[i][j], a0f[i], b1f[j >> 1][(j & 1) * 2],
                                 b1f[j >> 1][(j & 1) * 2 + 1]);
            }
            {
                uint32_t a1f[4][4];
#pragma unroll
                for (int i = 0; i < 4; i++)
                    ldsm4(a1f[i], sb + 1 * TILE_B + aOff + i * 1024);
#pragma unroll
                for (int i = 0; i < 4; i++)
#pragma unroll
                    for (int j = 0; j < 4; j++)
                        mma16816(acc[i][j], a1f[i], b0f[j >> 1][(j & 1) * 2],
                                 b0f[j >> 1][(j & 1) * 2 + 1]);
            }
        }
    }

    // ---------------- epilogue: smem-staged, coalesced global writes --------
    __syncthreads();

    const int rBase = warpM + (lane >> 2);
    const int cBaseH = warpN + (lane & 3) * 2;

    float bj[4][2];
#pragma unroll
    for (int j = 0; j < 4; j++)
#pragma unroll
        for (int t = 0; t < 2; t++) {
            int n = n0 + cBaseH + j * 8 + t;
            bj[j][t] = (SPLIT || n < Nreal) ? bias[bz * biasStr + n] : 0.0f;
        }

    if (SPLIT) {
#pragma unroll
        for (int i = 0; i < 4; i++)
#pragma unroll
            for (int j = 0; j < 4; j++)
#pragma unroll
                for (int half = 0; half < 2; half++) {
                    const int r = rBase + i * 16 + half * 8;
                    const int c = cBaseH + j * 8;
                    float v0 = fmaxf(acc[i][j][half * 2]     + bj[j][0], 0.0f);
                    float v1 = fmaxf(acc[i][j][half * 2 + 1] + bj[j][1], 0.0f);
                    __half a0, b0, a1, b1;
                    split2(v0, a0, b0);
                    split2(v1, a1, b1);
                    *(__half2*)(dsm + r * EPI_PITCH_H + c * 2) = __half2(a0, a1);
                    *(__half2*)(dsm + 128 * EPI_PITCH_H + r * EPI_PITCH_H + c * 2) = __half2(b0, b1);
                }
        __syncthreads();
#pragma unroll
        for (int it = 0; it < 8; it++) {
            int idx = tid + it * 256;
            int r = idx >> 4, c16 = idx & 15;
            float4 w0 = *(const float4*)(dsm + r * EPI_PITCH_H + c16 * 16);
            float4 w1 = *(const float4*)(dsm + 128 * EPI_PITCH_H + r * EPI_PITCH_H + c16 * 16);
            size_t gb = ((size_t)bz * B_ + m0 + r) * D_ + n0 + c16 * 8;
            *(float4*)&O0[gb] = w0;
            *(float4*)&O1[gb] = w1;
        }
    } else {
#pragma unroll
        for (int i = 0; i < 4; i++)
#pragma unroll
            for (int j = 0; j < 4; j++)
#pragma unroll
                for (int half = 0; half < 2; half++) {
                    const int r = rBase + i * 16 + half * 8;
                    const int c = cBaseH + j * 8;
                    float2 vv = make_float2(acc[i][j][half * 2]     + bj[j][0],
                                            acc[i][j][half * 2 + 1] + bj[j][1]);
                    *(float2*)(dsm + r * EPI_PITCH_F + c * 4) = vv;
                }
        __syncthreads();
#pragma unroll
        for (int it = 0; it < 16; it++) {
            int idx = tid + it * 256;
            int r = idx >> 5, c4 = idx & 31;
            float4 w = *(const float4*)(dsm + r * EPI_PITCH_F + c4 * 16);
            *(float4*)&outF[((size_t)(m0 + r) * K_ + bz) * outLd + n0 + c4 * 4] = w;
        }
    }
}

// ---------------------------------------------------------------------------
// Gating kernel v2 — register-resident. Thread t owns cols 4t..4t+3 of all
// 8 experts (C = 250*4; threads 250..255 idle via -inf logits).
// ---------------------------------------------------------------------------
__global__ void __launch_bounds__(256, 3) gating_kernel(
    const int* __restrict__ n_exp,
    float* __restrict__ out_logits,
    float* __restrict__ out_gates)
{
    __shared__ float sred[8][8];      // [warp][expert]
    __shared__ float sredG[8][36];    // [warp][pair]
    __shared__ float smax[K_], sZ[K_], sG[K_ * K_], sgate[K_];

    const int b = blockIdx.x, tid = threadIdx.x;
    const int w = tid >> 5, lane = tid & 31;
    const bool act = (tid < 250);
    const int c = tid * 4;

    const float* lrow = g_logits + (size_t)b * K_ * CP_;
    float4 lg[K_];
#pragma unroll
    for (int k = 0; k < K_; k++)
        lg[k] = act ? *(const float4*)(lrow + (size_t)k * CP_ + c)
                    : make_float4(-INFINITY, -INFINITY, -INFINITY, -INFINITY);

    // 1) per-expert max
#pragma unroll
    for (int k = 0; k < K_; k++) {
        float m = fmaxf(fmaxf(lg[k].x, lg[k].y), fmaxf(lg[k].z, lg[k].w));
#pragma unroll
        for (int o = 16; o > 0; o >>= 1) m = fmaxf(m, __shfl_xor_sync(0xffffffffu, m, o));
        if (lane == 0) sred[w][k] = m;
    }
    __syncthreads();
    if (tid < K_) {
        float m = sred[0][tid];
#pragma unroll
        for (int j = 1; j < 8; j++) m = fmaxf(m, sred[j][tid]);
        smax[tid] = m;
    }
    __syncthreads();

    // 2) exp + sum partials; gram partials
    float se[K_][4];
#pragma unroll
    for (int k = 0; k < K_; k++) {
        float m = smax[k];
        se[k][0] = __expf(lg[k].x - m);
        se[k][1] = __expf(lg[k].y - m);
        se[k][2] = __expf(lg[k].z - m);
        se[k][3] = __expf(lg[k].w - m);
        float z = se[k][0] + se[k][1] + se[k][2] + se[k][3];
#pragma unroll
        for (int o = 16; o > 0; o >>= 1) z += __shfl_xor_sync(0xffffffffu, z, o);
        if (lane == 0) sred[w][k] = z;
    }
    {
        int p = 0;
#pragma unroll
        for (int i = 0; i < K_; i++)
#pragma unroll
            for (int j = i; j < K_; j++) {
                float s = se[i][0] * se[j][0] + se[i][1] * se[j][1] +
                          se[i][2] * se[j][2] + se[i][3] * se[j][3];
#pragma unroll
                for (int o = 16; o > 0; o >>= 1) s += __shfl_xor_sync(0xffffffffu, s, o);
                if (lane == 0) sredG[w][p] = s;
                p++;
            }
    }
    __syncthreads();
    if (tid < K_) {
        float z = 0.0f;
#pragma unroll
        for (int j = 0; j < 8; j++) z += sred[j][tid];
        sZ[tid] = z;
    }
    __syncthreads();
    if (tid < 36) {
        float s = 0.0f;
#pragma unroll
        for (int j = 0; j < 8; j++) s += sredG[j][tid];
        int i = 0, q = tid;
        while (q >= K_ - i) { q -= (K_ - i); i++; }
        int jj = i + q;
        float g = s / (sZ[i] * sZ[jj]);
        sG[i * K_ + jj] = g;
        sG[jj * K_ + i] = g;
    }
    __syncthreads();

    // 3) greedy selection (serial, tid 0)
    if (tid == 0) {
        float Smat[K_][K_], conf[K_], nrm[K_];
#pragma unroll
        for (int i = 0; i < K_; i++) {
            nrm[i] = sqrtf(sG[i * K_ + i]) + EPSV;
            conf[i] = 1.0f / sZ[i];
        }
#pragma unroll
        for (int i = 0; i < K_; i++)
#pragma unroll
            for (int j = 0; j < K_; j++)
                Smat[i][j] = sG[i * K_ + j] / (nrm[i] * nrm[j]);

        int bi = 0; float bv = conf[0];
#pragma unroll
        for (int i = 1; i < K_; i++) if (conf[i] > bv) { bv = conf[i]; bi = i; }
        bool sel[K_];
#pragma unroll
        for (int i = 0; i < K_; i++) sel[i] = false;
        sel[bi] = true;

        int n = n_exp[b];
        for (int t = 1; t < K_; t++) {
            float dist[K_];
#pragma unroll
            for (int i = 0; i < K_; i++) {
                if (sel[i]) dist[i] = -INFINITY;
                else {
                    float ms = -INFINITY;
#pragma unroll
                    for (int j = 0; j < K_; j++)
                        if (sel[j]) ms = fmaxf(ms, Smat[i][j]);
                    dist[i] = 1.0f - ms;
                }
            }
            int ai = 0; float av = dist[0];
#pragma unroll
            for (int i = 1; i < K_; i++) if (dist[i] > av) { av = dist[i]; ai = i; }
            if (t < n) sel[ai] = true;
        }

        float gl[K_], gm = -INFINITY;
#pragma unroll
        for (int i = 0; i < K_; i++) {
            gl[i] = (sel[i] ? conf[i] : NEGV) / TEMPV;
            gm = fmaxf(gm, gl[i]);
        }
        float gs = 0.0f;
#pragma unroll
        for (int i = 0; i < K_; i++) { gl[i] = __expf(gl[i] - gm); gs += gl[i]; }
#pragma unroll
        for (int i = 0; i < K_; i++) sgate[i] = gl[i] / gs;
    }
    __syncthreads();

    // 4) gated combine straight from registers
    if (act) {
        float4 a4 = make_float4(0.f, 0.f, 0.f, 0.f);
#pragma unroll
        for (int k = 0; k < K_; k++) {
            float g = sgate[k];
            a4.x += g * lg[k].x; a4.y += g * lg[k].y;
            a4.z += g * lg[k].z; a4.w += g * lg[k].w;
        }
        *(float4*)(out_logits + (size_t)b * C_ + c) = a4;
    }
    if (tid < K_) out_gates[(size_t)b * K_ + tid] = sgate[tid];
}

// ---------------------------------------------------------------------------
extern "C" void kernel_launch(void* const* d_in, const int* in_sizes, int n_in,
                              void* d_out, int out_size)
{
    const float* z    = (const float*)d_in[0];
    const int*   nexp = (const int*)d_in[1];
    const float* W1   = (const float*)d_in[2];
    const float* b1   = (const float*)d_in[3];
    const float* W2   = (const float*)d_in[4];
    const float* b2   = (const float*)d_in[5];
    float* out = (float*)d_out;

    __half *z0, *z1, *w10, *w11, *w20, *w21, *h0, *h1;
    float* lg;
    cudaGetSymbolAddress((void**)&z0, g_z0);   cudaGetSymbolAddress((void**)&z1, g_z1);
    cudaGetSymbolAddress((void**)&w10, g_w1t0); cudaGetSymbolAddress((void**)&w11, g_w1t1);
    cudaGetSymbolAddress((void**)&w20, g_w2t0); cudaGetSymbolAddress((void**)&w21, g_w2t1);
    cudaGetSymbolAddress((void**)&h0, g_h0);   cudaGetSymbolAddress((void**)&h1, g_h1);
    cudaGetSymbolAddress((void**)&lg, g_logits);

    cudaFuncSetAttribute(tc_gemm<true>,  cudaFuncAttributeMaxDynamicSharedMemorySize, NSTAGE * STAGE_B);
    cudaFuncSetAttribute(tc_gemm<false>, cudaFuncAttributeMaxDynamicSharedMemorySize, NSTAGE * STAGE_B);

    // input conversions
    split2_kernel<<<(B_ * D_ / 4 + 255) / 256, 256>>>(z, z0, z1, B_ * D_ / 4);
    trsplit_kernel<<<dim3(D_ / 32, D_ / 32, K_), dim3(32, 8)>>>(W1, w10, w11, D_, D_);
    trsplit_kernel<<<dim3(CP_ / 32, D_ / 32, K_), dim3(32, 8)>>>(W2, w20, w21, C_, CP_);

    // GEMM1: h = relu(z @ W1 + b1), re-split into 2 fp16 limbs
    tc_gemm<true><<<dim3(D_ / 128, B_ / 128, K_), 256, NSTAGE * STAGE_B>>>(
        z0, z1, 0LL,
        w10, w11, (long long)D_ * D_,
        b1, D_, D_, nullptr, 0, h0, h1);

    // GEMM2: logits = h @ W2 + b2 (fp32, padded to CP_)
    tc_gemm<false><<<dim3(CP_ / 128, B_ / 128, K_), 256, NSTAGE * STAGE_B>>>(
        h0, h1, (long long)B_ * D_,
        w20, w21, (long long)CP_ * D_,
        b2, C_, C_, lg, CP_, nullptr, nullptr);

    // gating + combine
    gating_kernel<<<B_, 256>>>(nexp, out, out + (size_t)B_ * C_);
}

// round 12
// speedup vs baseline: 1.2836x; 1.1634x over previous
#include <cuda_runtime.h>
#include <cuda_fp16.h>
#include <cstdint>
#include <math.h>

#define B_ 8192
#define D_ 512
#define C_ 1000
#define CP_ 1024
#define K_ 8
#define EPSV 1e-8f
#define TEMPV 0.2f
#define NEGV -10000.0f

// ---------------------------------------------------------------------------
// Scratch (__device__ globals)
// ---------------------------------------------------------------------------
__device__ __half g_z0[(size_t)B_ * D_];
__device__ __half g_z1[(size_t)B_ * D_];
__device__ __half g_w1t0[(size_t)K_ * D_ * D_];
__device__ __half g_w1t1[(size_t)K_ * D_ * D_];
__device__ __half g_w2t0[(size_t)K_ * CP_ * D_];
__device__ __half g_w2t1[(size_t)K_ * CP_ * D_];
__device__ __half g_h0[(size_t)K_ * B_ * D_];
__device__ __half g_h1[(size_t)K_ * B_ * D_];
__device__ float g_logits[(size_t)B_ * K_ * CP_];

// ---------------------------------------------------------------------------
// PTX helpers
// ---------------------------------------------------------------------------
__device__ __forceinline__ uint32_t smem_u32(const void* p) {
    uint32_t a;
    asm("{ .reg .u64 t; cvta.to.shared.u64 t, %1; cvt.u32.u64 %0, t; }" : "=r"(a) : "l"(p));
    return a;
}
__device__ __forceinline__ void cp_async16(uint32_t s, const void* g) {
    asm volatile("cp.async.cg.shared.global [%0], [%1], 16;" :: "r"(s), "l"(g));
}
__device__ __forceinline__ void cp_commit() { asm volatile("cp.async.commit_group;"); }
template <int N>
__device__ __forceinline__ void cp_wait() { asm volatile("cp.async.wait_group %0;" :: "n"(N)); }

__device__ __forceinline__ void ldsm4(uint32_t* r, uint32_t addr) {
    asm volatile("ldmatrix.sync.aligned.m8n8.x4.shared.b16 {%0,%1,%2,%3}, [%4];"
                 : "=r"(r[0]), "=r"(r[1]), "=r"(r[2]), "=r"(r[3]) : "r"(addr));
}
__device__ __forceinline__ void mma16816(float* c, const uint32_t* a, uint32_t b0, uint32_t b1) {
    asm volatile(
        "mma.sync.aligned.m16n8k16.row.col.f32.f16.f16.f32 "
        "{%0,%1,%2,%3}, {%4,%5,%6,%7}, {%8,%9}, {%0,%1,%2,%3};"
        : "+f"(c[0]), "+f"(c[1]), "+f"(c[2]), "+f"(c[3])
        : "r"(a[0]), "r"(a[1]), "r"(a[2]), "r"(a[3]), "r"(b0), "r"(b1));
}

// 2-limb fp16 split: x = a + b + O(2^-22 |x|)
__device__ __forceinline__ void split2(float x, __half& a, __half& b) {
    a = __float2half_rn(x);
    b = __float2half_rn(x - __half2float(a));
}

// ---------------------------------------------------------------------------
// Merged conversion kernel: one launch does all three jobs.
//   blocks [0, NB_Z)            : split2 of z (flat)
//   blocks [NB_Z, NB_Z+NB_W1)   : transpose+split W1
//   blocks [.., +NB_W2)         : transpose+split W2
// ---------------------------------------------------------------------------
#define NB_Z  (B_ * D_ / 4 / 256)            // 4096
#define NB_W1 ((D_ / 32) * (D_ / 32) * K_)   // 2048
#define NB_W2 ((CP_ / 32) * (D_ / 32) * K_)  // 4096

__device__ __forceinline__ void trsplit_body(
    const float* __restrict__ in, __half* __restrict__ o0, __half* __restrict__ o1,
    int Nin, int Npad, int bx, int by, int k, int tid)
{
    __shared__ float t[32][33];
    const int n0 = bx * 32, d0 = by * 32;
    const int tx = tid & 31, ty = tid >> 5;
    const float* src = in + (size_t)k * D_ * Nin;
#pragma unroll
    for (int r = 0; r < 4; r++) {
        int d = d0 + ty + r * 8, n = n0 + tx;
        t[ty + r * 8][tx] = (n < Nin) ? src[(size_t)d * Nin + n] : 0.0f;
    }
    __syncthreads();
    size_t obase = (size_t)k * Npad * D_;
#pragma unroll
    for (int r = 0; r < 4; r++) {
        int nl = ty + r * 8;
        float v = t[tx][nl];
        __half a, b;
        split2(v, a, b);
        size_t oi = obase + (size_t)(n0 + nl) * D_ + d0 + tx;
        o0[oi] = a; o1[oi] = b;
    }
}

__global__ void __launch_bounds__(256) convert_all_kernel(
    const float* __restrict__ z, const float* __restrict__ W1,
    const float* __restrict__ W2,
    __half* __restrict__ z0, __half* __restrict__ z1,
    __half* __restrict__ w10, __half* __restrict__ w11,
    __half* __restrict__ w20, __half* __restrict__ w21)
{
    const int blk = blockIdx.x;
    const int tid = threadIdx.x;
    if (blk < NB_Z) {
        int i = blk * 256 + tid;
        float4 v = ((const float4*)z)[i];
        __half a0, b0, a1, b1, a2, b2, a3, b3;
        split2(v.x, a0, b0); split2(v.y, a1, b1);
        split2(v.z, a2, b2); split2(v.w, a3, b3);
        ((__half2*)z0)[i * 2]     = __half2(a0, a1);
        ((__half2*)z0)[i * 2 + 1] = __half2(a2, a3);
        ((__half2*)z1)[i * 2]     = __half2(b0, b1);
        ((__half2*)z1)[i * 2 + 1] = __half2(b2, b3);
    } else if (blk < NB_Z + NB_W1) {
        int r = blk - NB_Z;                 // (bx, by, k): bx in 16, by in 16, k in 8
        int bx = r & 15; r >>= 4;
        int by = r & 15; r >>= 4;
        trsplit_body(W1, w10, w11, D_, D_, bx, by, r, tid);
    } else {
        int r = blk - NB_Z - NB_W1;         // (bx, by, k): bx in 32, by in 16, k in 8
        int bx = r & 31; r >>= 5;
        int by = r & 15; r >>= 4;
        trsplit_body(W2, w20, w21, C_, CP_, bx, by, r, tid);
    }
}

// ---------------------------------------------------------------------------
// HMMA fp16 GEMM with 3-product 2-limb split. (unchanged — proven)
// ---------------------------------------------------------------------------
#define TILE_B 8192
#define STAGE_B (4 * TILE_B)
#define NSTAGE 3
#define NCHUNK 16
#define EPI_PITCH_H 272
#define EPI_PITCH_F 528

template <bool SPLIT>
__global__ void __launch_bounds__(256, 2) tc_gemm(
    const __half* __restrict__ A0, const __half* __restrict__ A1, long long aStr,
    const __half* __restrict__ B0, const __half* __restrict__ B1, long long bStr,
    const float* __restrict__ bias, int biasStr, int Nreal,
    float* __restrict__ outF, int outLd,
    __half* __restrict__ O0, __half* __restrict__ O1)
{
    extern __shared__ __align__(16) char dsm[];
    const uint32_t sbase = smem_u32(dsm);

    const int tid = threadIdx.x;
    const int warp = tid >> 5, lane = tid & 31;
    const int bz = blockIdx.z;
    const int m0 = blockIdx.y * 128, n0 = blockIdx.x * 128;
    const int warpM = (warp >> 2) * 64;
    const int warpN = (warp & 3) * 32;

    const char* gp[4];
    gp[0] = (const char*)A0 + ((size_t)bz * aStr + (size_t)m0 * D_) * 2;
    gp[1] = (const char*)A1 + ((size_t)bz * aStr + (size_t)m0 * D_) * 2;
    gp[2] = (const char*)B0 + ((size_t)bz * bStr + (size_t)n0 * D_) * 2;
    gp[3] = (const char*)B1 + ((size_t)bz * bStr + (size_t)n0 * D_) * 2;

    const int ldRow0 = tid >> 2, ldC0 = tid & 3;
    const int ldRow1 = (tid + 256) >> 2, ldC1 = (tid + 256) & 3;
    const uint32_t ldDst0 = (uint32_t)ldRow0 * 64 + (uint32_t)((ldC0 ^ ((ldRow0 >> 1) & 3)) << 4);
    const uint32_t ldDst1 = (uint32_t)ldRow1 * 64 + (uint32_t)((ldC1 ^ ((ldRow1 >> 1) & 3)) << 4);
    const size_t ldSrc0 = (size_t)ldRow0 * 1024 + ldC0 * 16;
    const size_t ldSrc1 = (size_t)ldRow1 * 1024 + ldC1 * 16;

    auto load_stage = [&](int kk, int buf) {
        const size_t koff = (size_t)kk * 64;
#pragma unroll
        for (int t = 0; t < 4; t++) {
            uint32_t sb = sbase + buf * STAGE_B + t * TILE_B;
            const char* g = gp[t] + koff;
            cp_async16(sb + ldDst0, g + ldSrc0);
            cp_async16(sb + ldDst1, g + ldSrc1);
        }
        cp_commit();
    };

    float acc[4][4][4];
#pragma unroll
    for (int i = 0; i < 4; i++)
#pragma unroll
        for (int j = 0; j < 4; j++)
#pragma unroll
            for (int r = 0; r < 4; r++) acc[i][j][r] = 0.0f;

    load_stage(0, 0);
    load_stage(1, 1);

    const int rowA = warpM + (lane & 15);
    const uint32_t swA = (uint32_t)((rowA >> 1) & 3);
    const uint32_t cA = (uint32_t)(lane >> 4);
    const uint32_t aBase = (uint32_t)rowA * 64;

    const int rowB = warpN + (lane & 7) + ((lane >> 4) & 1) * 8;
    const uint32_t swB = (uint32_t)((rowB >> 1) & 3);
    const uint32_t cB = (uint32_t)((lane >> 3) & 1);
    const uint32_t bBase = (uint32_t)rowB * 64;

    for (int kk = 0; kk < NCHUNK; kk++) {
        if (kk == NCHUNK - 1) cp_wait<0>(); else cp_wait<1>();
        __syncthreads();
        if (kk + 2 < NCHUNK) load_stage(kk + 2, (kk + 2) % NSTAGE);

        const uint32_t sb = sbase + (kk % NSTAGE) * STAGE_B;

#pragma unroll
        for (int ks = 0; ks < 2; ks++) {
            const uint32_t aOff = aBase + (((ks * 2 + cA) ^ swA) << 4);
            const uint32_t bOff = bBase + (((ks * 2 + cB) ^ swB) << 4);
            uint32_t a0f[4][4], b0f[2][4];
#pragma unroll
            for (int i = 0; i < 4; i++)
                ldsm4(a0f[i], sb + 0 * TILE_B + aOff + i * 1024);
#pragma unroll
            for (int jp = 0; jp < 2; jp++)
                ldsm4(b0f[jp], sb + 2 * TILE_B + bOff + jp * 1024);
#pragma unroll
            for (int i = 0; i < 4; i++)
#pragma unroll
                for (int j = 0; j < 4; j++)
                    mma16816(acc[i][j], a0f[i], b0f[j >> 1][(j & 1) * 2],
                             b0f[j >> 1][(j & 1) * 2 + 1]);
            {
                uint32_t b1f[2][4];
#pragma unroll
                for (int jp = 0; jp < 2; jp++)
                    ldsm4(b1f[jp], sb + 3 * TILE_B + bOff + jp * 1024);
#pragma unroll
                for (int i = 0; i < 4; i++)
#pragma unroll
                    for (int j = 0; j < 4; j++)
                        mma16816(acc[i][j], a0f[i], b1f[j >> 1][(j & 1) * 2],
                                 b1f[j >> 1][(j & 1) * 2 + 1]);
            }
            {
                uint32_t a1f[4][4];
#pragma unroll
                for (int i = 0; i < 4; i++)
                    ldsm4(a1f[i], sb + 1 * TILE_B + aOff + i * 1024);
#pragma unroll
                for (int i = 0; i < 4; i++)
#pragma unroll
                    for (int j = 0; j < 4; j++)
                        mma16816(acc[i][j], a1f[i], b0f[j >> 1][(j & 1) * 2],
                                 b0f[j >> 1][(j & 1) * 2 + 1]);
            }
        }
    }

    // ---------------- epilogue: smem-staged, coalesced global writes --------
    __syncthreads();

    const int rBase = warpM + (lane >> 2);
    const int cBaseH = warpN + (lane & 3) * 2;

    float bj[4][2];
#pragma unroll
    for (int j = 0; j < 4; j++)
#pragma unroll
        for (int t = 0; t < 2; t++) {
            int n = n0 + cBaseH + j * 8 + t;
            bj[j][t] = (SPLIT || n < Nreal) ? bias[bz * biasStr + n] : 0.0f;
        }

    if (SPLIT) {
#pragma unroll
        for (int i = 0; i < 4; i++)
#pragma unroll
            for (int j = 0; j < 4; j++)
#pragma unroll
                for (int half = 0; half < 2; half++) {
                    const int r = rBase + i * 16 + half * 8;
                    const int c = cBaseH + j * 8;
                    float v0 = fmaxf(acc[i][j][half * 2]     + bj[j][0], 0.0f);
                    float v1 = fmaxf(acc[i][j][half * 2 + 1] + bj[j][1], 0.0f);
                    __half a0, b0, a1, b1;
                    split2(v0, a0, b0);
                    split2(v1, a1, b1);
                    *(__half2*)(dsm + r * EPI_PITCH_H + c * 2) = __half2(a0, a1);
                    *(__half2*)(dsm + 128 * EPI_PITCH_H + r * EPI_PITCH_H + c * 2) = __half2(b0, b1);
                }
        __syncthreads();
#pragma unroll
        for (int it = 0; it < 8; it++) {
            int idx = tid + it * 256;
            int r = idx >> 4, c16 = idx & 15;
            float4 w0 = *(const float4*)(dsm + r * EPI_PITCH_H + c16 * 16);
            float4 w1 = *(const float4*)(dsm + 128 * EPI_PITCH_H + r * EPI_PITCH_H + c16 * 16);
            size_t gb = ((size_t)bz * B_ + m0 + r) * D_ + n0 + c16 * 8;
            *(float4*)&O0[gb] = w0;
            *(float4*)&O1[gb] = w1;
        }
    } else {
#pragma unroll
        for (int i = 0; i < 4; i++)
#pragma unroll
            for (int j = 0; j < 4; j++)
#pragma unroll
                for (int half = 0; half < 2; half++) {
                    const int r = rBase + i * 16 + half * 8;
                    const int c = cBaseH + j * 8;
                    float2 vv = make_float2(acc[i][j][half * 2]     + bj[j][0],
                                            acc[i][j][half * 2 + 1] + bj[j][1]);
                    *(float2*)(dsm + r * EPI_PITCH_F + c * 4) = vv;
                }
        __syncthreads();
#pragma unroll
        for (int it = 0; it < 16; it++) {
            int idx = tid + it * 256;
            int r = idx >> 5, c4 = idx & 31;
            float4 w = *(const float4*)(dsm + r * EPI_PITCH_F + c4 * 16);
            *(float4*)&outF[((size_t)(m0 + r) * K_ + bz) * outLd + n0 + c4 * 4] = w;
        }
    }
}

// ---------------------------------------------------------------------------
// Gating kernel v3 — register-resident; selection parallelized over 8 lanes.
// ---------------------------------------------------------------------------
__global__ void __launch_bounds__(256, 3) gating_kernel(
    const int* __restrict__ n_exp,
    float* __restrict__ out_logits,
    float* __restrict__ out_gates)
{
    __shared__ float sred[8][8];      // [warp][expert]
    __shared__ float sredG[8][36];    // [warp][pair]
    __shared__ float smax[K_], sZ[K_], sG[K_ * K_], sgate[K_];

    const int b = blockIdx.x, tid = threadIdx.x;
    const int w = tid >> 5, lane = tid & 31;
    const bool act = (tid < 250);
    const int c = tid * 4;

    const float* lrow = g_logits + (size_t)b * K_ * CP_;
    float4 lg[K_];
#pragma unroll
    for (int k = 0; k < K_; k++)
        lg[k] = act ? *(const float4*)(lrow + (size_t)k * CP_ + c)
                    : make_float4(-INFINITY, -INFINITY, -INFINITY, -INFINITY);

    // 1) per-expert max
#pragma unroll
    for (int k = 0; k < K_; k++) {
        float m = fmaxf(fmaxf(lg[k].x, lg[k].y), fmaxf(lg[k].z, lg[k].w));
#pragma unroll
        for (int o = 16; o > 0; o >>= 1) m = fmaxf(m, __shfl_xor_sync(0xffffffffu, m, o));
        if (lane == 0) sred[w][k] = m;
    }
    __syncthreads();
    if (tid < K_) {
        float m = sred[0][tid];
#pragma unroll
        for (int j = 1; j < 8; j++) m = fmaxf(m, sred[j][tid]);
        smax[tid] = m;
    }
    __syncthreads();

    // 2) exp + sum partials; gram partials
    float se[K_][4];
#pragma unroll
    for (int k = 0; k < K_; k++) {
        float m = smax[k];
        se[k][0] = __expf(lg[k].x - m);
        se[k][1] = __expf(lg[k].y - m);
        se[k][2] = __expf(lg[k].z - m);
        se[k][3] = __expf(lg[k].w - m);
        float z = se[k][0] + se[k][1] + se[k][2] + se[k][3];
#pragma unroll
        for (int o = 16; o > 0; o >>= 1) z += __shfl_xor_sync(0xffffffffu, z, o);
        if (lane == 0) sred[w][k] = z;
    }
    {
        int p = 0;
#pragma unroll
        for (int i = 0; i < K_; i++)
#pragma unroll
            for (int j = i; j < K_; j++) {
                float s = se[i][0] * se[j][0] + se[i][1] * se[j][1] +
                          se[i][2] * se[j][2] + se[i][3] * se[j][3];
#pragma unroll
                for (int o = 16; o > 0; o >>= 1) s += __shfl_xor_sync(0xffffffffu, s, o);
                if (lane == 0) sredG[w][p] = s;
                p++;
            }
    }
    __syncthreads();
    if (tid < K_) {
        float z = 0.0f;
#pragma unroll
        for (int j = 0; j < 8; j++) z += sred[j][tid];
        sZ[tid] = z;
    }
    __syncthreads();
    if (tid < 36) {
        float s = 0.0f;
#pragma unroll
        for (int j = 0; j < 8; j++) s += sredG[j][tid];
        int i = 0, q = tid;
        while (q >= K_ - i) { q -= (K_ - i); i++; }
        int jj = i + q;
        float g = s / (sZ[i] * sZ[jj]);
        sG[i * K_ + jj] = g;
        sG[jj * K_ + i] = g;
    }
    __syncthreads();

    // 3) greedy selection — lanes 0..7 of warp 0 (lane = candidate expert i)
    if (tid < 8) {
        const unsigned MSK = 0xFFu;
        const int i = tid;
        float nrmv = sqrtf(sG[i * K_ + i]) + EPSV;
        float confv = 1.0f / sZ[i];
        float Srow[K_];
#pragma unroll
        for (int j = 0; j < K_; j++) {
            float nrmj = __shfl_sync(MSK, nrmv, j, 8);
            Srow[j] = sG[i * K_ + j] / (nrmv * nrmj);
        }

        // argmax conf (first-index tie-break)
        float bv = confv; int bi = i;
#pragma unroll
        for (int o = 4; o > 0; o >>= 1) {
            float ov = __shfl_down_sync(MSK, bv, o, 8);
            int oi = __shfl_down_sync(MSK, bi, o, 8);
            if (ov > bv || (ov == bv && oi < bi)) { bv = ov; bi = oi; }
        }
        bi = __shfl_sync(MSK, bi, 0, 8);
        unsigned selMask = 1u << bi;

        int n = n_exp[b];
        for (int t = 1; t < K_; t++) {
            float dist;
            if (selMask & (1u << i)) dist = -INFINITY;
            else {
                float ms = -INFINITY;
#pragma unroll
                for (int j = 0; j < K_; j++)
                    if (selMask & (1u << j)) ms = fmaxf(ms, Srow[j]);
                dist = 1.0f - ms;
            }
            float av = dist; int ai = i;
#pragma unroll
            for (int o = 4; o > 0; o >>= 1) {
                float ov = __shfl_down_sync(MSK, av, o, 8);
                int oi = __shfl_down_sync(MSK, ai, o, 8);
                if (ov > av || (ov == av && oi < ai)) { av = ov; ai = oi; }
            }
            ai = __shfl_sync(MSK, ai, 0, 8);
            if (t < n) selMask |= 1u << ai;
        }

        // gate softmax over 8 lanes
        float gl = ((selMask >> i) & 1u) ? confv / TEMPV : NEGV / TEMPV;
        float gm = gl;
#pragma unroll
        for (int o = 4; o > 0; o >>= 1) gm = fmaxf(gm, __shfl_xor_sync(MSK, gm, o, 8));
        float ge = __expf(gl - gm);
        float gs = ge;
#pragma unroll
        for (int o = 4; o > 0; o >>= 1) gs += __shfl_xor_sync(MSK, gs, o, 8);
        sgate[i] = ge / gs;
    }
    __syncthreads();

    // 4) gated combine straight from registers
    if (act) {
        float4 a4 = make_float4(0.f, 0.f, 0.f, 0.f);
#pragma unroll
        for (int k = 0; k < K_; k++) {
            float g = sgate[k];
            a4.x += g * lg[k].x; a4.y += g * lg[k].y;
            a4.z += g * lg[k].z; a4.w += g * lg[k].w;
        }
        *(float4*)(out_logits + (size_t)b * C_ + c) = a4;
    }
    if (tid < K_) out_gates[(size_t)b * K_ + tid] = sgate[tid];
}

// ---------------------------------------------------------------------------
extern "C" void kernel_launch(void* const* d_in, const int* in_sizes, int n_in,
                              void* d_out, int out_size)
{
    const float* z    = (const float*)d_in[0];
    const int*   nexp = (const int*)d_in[1];
    const float* W1   = (const float*)d_in[2];
    const float* b1   = (const float*)d_in[3];
    const float* W2   = (const float*)d_in[4];
    const float* b2   = (const float*)d_in[5];
    float* out = (float*)d_out;

    __half *z0, *z1, *w10, *w11, *w20, *w21, *h0, *h1;
    float* lg;
    cudaGetSymbolAddress((void**)&z0, g_z0);   cudaGetSymbolAddress((void**)&z1, g_z1);
    cudaGetSymbolAddress((void**)&w10, g_w1t0); cudaGetSymbolAddress((void**)&w11, g_w1t1);
    cudaGetSymbolAddress((void**)&w20, g_w2t0); cudaGetSymbolAddress((void**)&w21, g_w2t1);
    cudaGetSymbolAddress((void**)&h0, g_h0);   cudaGetSymbolAddress((void**)&h1, g_h1);
    cudaGetSymbolAddress((void**)&lg, g_logits);

    cudaFuncSetAttribute(tc_gemm<true>,  cudaFuncAttributeMaxDynamicSharedMemorySize, NSTAGE * STAGE_B);
    cudaFuncSetAttribute(tc_gemm<false>, cudaFuncAttributeMaxDynamicSharedMemorySize, NSTAGE * STAGE_B);

    // merged input conversions (z, W1, W2 in one launch)
    convert_all_kernel<<<NB_Z + NB_W1 + NB_W2, 256>>>(
        z, W1, W2, z0, z1, w10, w11, w20, w21);

    // GEMM1: h = relu(z @ W1 + b1), re-split into 2 fp16 limbs
    tc_gemm<true><<<dim3(D_ / 128, B_ / 128, K_), 256, NSTAGE * STAGE_B>>>(
        z0, z1, 0LL,
        w10, w11, (long long)D_ * D_,
        b1, D_, D_, nullptr, 0, h0, h1);

    // GEMM2: logits = h @ W2 + b2 (fp32, padded to CP_)
    tc_gemm<false><<<dim3(CP_ / 128, B_ / 128, K_), 256, NSTAGE * STAGE_B>>>(
        h0, h1, (long long)B_ * D_,
        w20, w21, (long long)CP_ * D_,
        b2, C_, C_, lg, CP_, nullptr, nullptr);

    // gating + combine
    gating_kernel<<<B_, 256>>>(nexp, out, out + (size_t)B_ * C_);
}